// round 4
// baseline (speedup 1.0000x reference)
#include <cuda_runtime.h>
#include <stdint.h>

#define SCALE_F 0.125f

// scratch
__device__ float g_q[2ull * 64 * 1024 * 64];
__device__ float g_k[2ull * 64 * 1024 * 64];
__device__ float g_v[2ull * 64 * 1024 * 64];
__device__ float g_s[2ull * 64 * 1024 * 1024];
__device__ float g_att2[2ull * 8192 * 512];

#define RIH (64LL * 1024 * 64)
#define RIS (64LL * 1024 * 1024)
#define RIO (8192LL * 512)

__device__ __forceinline__ uint32_t f2tf32(float f) {
    uint32_t u;
    asm("cvt.rna.tf32.f32 %0, %1;" : "=r"(u) : "f"(f));
    return u;
}

#define MMA_TF32(C, A, B) \
    asm volatile("mma.sync.aligned.m16n8k8.row.col.f32.tf32.tf32.f32 " \
                 "{%0,%1,%2,%3},{%4,%5,%6,%7},{%8,%9},{%0,%1,%2,%3};" \
                 : "+f"((C)[0]), "+f"((C)[1]), "+f"((C)[2]), "+f"((C)[3]) \
                 : "r"((A)[0]), "r"((A)[1]), "r"((A)[2]), "r"((A)[3]), \
                   "r"((B)[0]), "r"((B)[1]))

// Complex GEMM, tf32 tensor cores, double-buffered pipeline.
// C_r = alpha*(Ar.Br^T + S1*Ai.Bi^T)(+b_r) ; C_i = alpha*(Ai.Br^T + S2*Ar.Bi^T)(+b_i)
// A:[M][K] rm. B: BT=0 -> [N][K] rm ; BT=1 -> [K][N] rm (N=64, K-stride 64).
// EPI: 0 = row-major C[m][N]; 1 = QKV head-layout split (Cr=q, Ck=k, Cv=v);
//      2 = PV -> [t*8+b][h*64+d] layout.
template<int S1, int S2, bool BIAS, int EPI, bool BT>
__global__ __launch_bounds__(256, 2)
void gemm_cplx_mma(const float* __restrict__ Ar, const float* __restrict__ Ai,
                   const float* __restrict__ Br, const float* __restrict__ Bi,
                   const float* __restrict__ bR, const float* __restrict__ bI,
                   float* __restrict__ Cr, float* __restrict__ Ci,
                   float* __restrict__ Ck, float* __restrict__ Cv,
                   int N, int K, float alpha,
                   long long bsA, long long bsB, long long bsC)
{
    extern __shared__ uint32_t sm[];
    const int ASZ = 128 * 24;                 // words per A buffer (r or i)
    const int BSZ = BT ? 16 * 72 : 64 * 24;   // words per B buffer
    uint32_t* sAr = sm;
    uint32_t* sAi = sm + 2 * ASZ;
    uint32_t* sBr = sm + 4 * ASZ;
    uint32_t* sBi = sm + 4 * ASZ + 2 * BSZ;

    const int tid  = threadIdx.x;
    const int lane = tid & 31;
    const int wid  = tid >> 5;
    const int wm   = (wid >> 1) * 32;
    const int wn   = (wid & 1) * 32;
    const int g    = lane >> 2;
    const int t    = lane & 3;
    const int m0   = blockIdx.y * 128;
    const int n0   = blockIdx.x * 64;

    Ar += (long long)blockIdx.z * bsA;  Ai += (long long)blockIdx.z * bsA;
    Br += (long long)blockIdx.z * bsB;  Bi += (long long)blockIdx.z * bsB;
    Cr += (long long)blockIdx.z * bsC;  Ci += (long long)blockIdx.z * bsC;

    // loader indices
    const int arow = tid >> 1, ahalf = tid & 1;
    const float* gAr = Ar + (long long)(m0 + arow) * K + ahalf * 8;
    const float* gAi = Ai + (long long)(m0 + arow) * K + ahalf * 8;
    const float* gBr;
    const float* gBi;
    int sidx = 0, dq = 0;
    if (BT) {
        sidx = tid >> 4; dq = (tid & 15) * 4;
        gBr = Br + sidx * 64 + dq;
        gBi = Bi + sidx * 64 + dq;
    } else {
        int brow = tid >> 1, bhalf = tid & 1;
        gBr = Br + (long long)(n0 + brow) * K + bhalf * 8;
        gBi = Bi + (long long)(n0 + brow) * K + bhalf * 8;
    }

    float4 Ar0, Ar1, Ai0, Ai1;           // staged A (this thread's 2x8 k-chunk)
    float4 Br0, Br1, Bi0, Bi1;           // staged B

    float cr[2][4][4];
    float ci[2][4][4];
    #pragma unroll
    for (int a = 0; a < 2; a++)
        #pragma unroll
        for (int b = 0; b < 4; b++)
            #pragma unroll
            for (int c = 0; c < 4; c++) { cr[a][b][c] = 0.f; ci[a][b][c] = 0.f; }

#define LDG_TILE(K0) do {                                                      \
    Ar0 = *(const float4*)(gAr + (K0));  Ar1 = *(const float4*)(gAr + (K0) + 4); \
    Ai0 = *(const float4*)(gAi + (K0));  Ai1 = *(const float4*)(gAi + (K0) + 4); \
    if (BT) {                                                                  \
        Br0 = *(const float4*)(gBr + (long long)(K0) * 64);                    \
        Bi0 = *(const float4*)(gBi + (long long)(K0) * 64);                    \
    } else if (tid < 128) {                                                    \
        Br0 = *(const float4*)(gBr + (K0));  Br1 = *(const float4*)(gBr + (K0) + 4); \
        Bi0 = *(const float4*)(gBi + (K0));  Bi1 = *(const float4*)(gBi + (K0) + 4); \
    }                                                                          \
} while (0)

#define STS_PAIRS(base, v0, v1) do {                                           \
    uint4 u;                                                                   \
    u.x = f2tf32((v0).x); u.y = f2tf32((v1).x);                                \
    u.z = f2tf32((v0).y); u.w = f2tf32((v1).y);                                \
    *(uint4*)(base) = u;                                                       \
    u.x = f2tf32((v0).z); u.y = f2tf32((v1).z);                                \
    u.z = f2tf32((v0).w); u.w = f2tf32((v1).w);                                \
    *(uint4*)((base) + 4) = u;                                                 \
} while (0)

#define STS_TILE(P) do {                                                       \
    uint32_t* ab = sAr + (P) * ASZ + arow * 24 + ahalf * 8;                    \
    STS_PAIRS(ab, Ar0, Ar1);                                                   \
    ab = sAi + (P) * ASZ + arow * 24 + ahalf * 8;                              \
    STS_PAIRS(ab, Ai0, Ai1);                                                   \
    if (BT) {                                                                  \
        uint32_t* bb = sBr + (P) * BSZ + sidx * 72 + dq;                       \
        uint4 u;                                                               \
        u.x = f2tf32(Br0.x); u.y = f2tf32(Br0.y); u.z = f2tf32(Br0.z); u.w = f2tf32(Br0.w); \
        *(uint4*)bb = u;                                                       \
        bb = sBi + (P) * BSZ + sidx * 72 + dq;                                 \
        u.x = f2tf32(Bi0.x); u.y = f2tf32(Bi0.y); u.z = f2tf32(Bi0.z); u.w = f2tf32(Bi0.w); \
        *(uint4*)bb = u;                                                       \
    } else if (tid < 128) {                                                    \
        uint32_t* bb = sBr + (P) * BSZ + (tid >> 1) * 24 + (tid & 1) * 8;      \
        STS_PAIRS(bb, Br0, Br1);                                               \
        bb = sBi + (P) * BSZ + (tid >> 1) * 24 + (tid & 1) * 8;                \
        STS_PAIRS(bb, Bi0, Bi1);                                               \
    }                                                                          \
} while (0)

    LDG_TILE(0);
    STS_TILE(0);
    __syncthreads();

    const int nk = K / 16;
    for (int it = 0; it < nk; it++) {
        const int p = it & 1;
        if (it + 1 < nk) LDG_TILE((it + 1) * 16);

        #pragma unroll
        for (int kk = 0; kk < 2; kk++) {
            uint32_t far0[4], far1[4], fai0[4], fai1[4];
            {
                const uint32_t* aR = sAr + p * ASZ + kk * 8 + t * 2;
                const uint32_t* aI = sAi + p * ASZ + kk * 8 + t * 2;
                uint2 x0 = *(const uint2*)(aR + (wm + g) * 24);
                uint2 x1 = *(const uint2*)(aR + (wm + g + 8) * 24);
                far0[0] = x0.x; far0[1] = x1.x; far0[2] = x0.y; far0[3] = x1.y;
                x0 = *(const uint2*)(aR + (wm + 16 + g) * 24);
                x1 = *(const uint2*)(aR + (wm + 24 + g) * 24);
                far1[0] = x0.x; far1[1] = x1.x; far1[2] = x0.y; far1[3] = x1.y;
                x0 = *(const uint2*)(aI + (wm + g) * 24);
                x1 = *(const uint2*)(aI + (wm + g + 8) * 24);
                fai0[0] = x0.x; fai0[1] = x1.x; fai0[2] = x0.y; fai0[3] = x1.y;
                x0 = *(const uint2*)(aI + (wm + 16 + g) * 24);
                x1 = *(const uint2*)(aI + (wm + 24 + g) * 24);
                fai1[0] = x0.x; fai1[1] = x1.x; fai1[2] = x0.y; fai1[3] = x1.y;
            }
            #pragma unroll
            for (int nt = 0; nt < 4; nt++) {
                uint32_t fbr[2], fbi[2];
                if (BT) {
                    const uint32_t* bb = sBr + p * BSZ + (kk * 8 + t) * 72 + wn + nt * 8 + g;
                    fbr[0] = bb[0]; fbr[1] = bb[4 * 72];
                    bb = sBi + p * BSZ + (kk * 8 + t) * 72 + wn + nt * 8 + g;
                    fbi[0] = bb[0]; fbi[1] = bb[4 * 72];
                } else {
                    const uint32_t* bb = sBr + p * BSZ + (wn + nt * 8 + g) * 24 + kk * 8 + t * 2;
                    uint2 v = *(const uint2*)bb;
                    fbr[0] = v.x; fbr[1] = v.y;
                    bb = sBi + p * BSZ + (wn + nt * 8 + g) * 24 + kk * 8 + t * 2;
                    v = *(const uint2*)bb;
                    fbi[0] = v.x; fbi[1] = v.y;
                }
                MMA_TF32(cr[0][nt], far0, fbr);
                MMA_TF32(cr[1][nt], far1, fbr);
                MMA_TF32(ci[0][nt], fai0, fbr);
                MMA_TF32(ci[1][nt], fai1, fbr);
                if (S2 > 0) {
                    MMA_TF32(ci[0][nt], far0, fbi);
                    MMA_TF32(ci[1][nt], far1, fbi);
                } else {
                    MMA_TF32(cr[0][nt], fai0, fbi);
                    MMA_TF32(cr[1][nt], fai1, fbi);
                }
                fbi[0] ^= 0x80000000u; fbi[1] ^= 0x80000000u;
                if (S2 > 0) {
                    MMA_TF32(cr[0][nt], fai0, fbi);
                    MMA_TF32(cr[1][nt], fai1, fbi);
                } else {
                    MMA_TF32(ci[0][nt], far0, fbi);
                    MMA_TF32(ci[1][nt], far1, fbi);
                }
            }
        }

        if (it + 1 < nk) {
            __syncthreads();
            STS_TILE(p ^ 1);
            __syncthreads();
        }
    }

    // ---- epilogue ----
    #pragma unroll
    for (int mt = 0; mt < 2; mt++) {
        #pragma unroll
        for (int nt = 0; nt < 4; nt++) {
            const int colL = wn + nt * 8 + 2 * t;
            float br0 = 0.f, br1 = 0.f, bi0 = 0.f, bi1 = 0.f;
            if (BIAS) {
                int col = n0 + colL;
                br0 = bR[col]; br1 = bR[col + 1];
                bi0 = bI[col]; bi1 = bI[col + 1];
            }
            #pragma unroll
            for (int rh = 0; rh < 2; rh++) {
                const int r = m0 + wm + mt * 16 + g + rh * 8;
                float2 vr, vi;
                vr.x = cr[mt][nt][rh * 2 + 0] * alpha + br0;
                vr.y = cr[mt][nt][rh * 2 + 1] * alpha + br1;
                vi.x = ci[mt][nt][rh * 2 + 0] * alpha + bi0;
                vi.y = ci[mt][nt][rh * 2 + 1] * alpha + bi1;
                if (EPI == 0) {
                    long long o = (long long)r * N + n0 + colL;
                    *(float2*)(Cr + o) = vr;
                    *(float2*)(Ci + o) = vi;
                } else if (EPI == 1) {
                    int col = n0 + colL;
                    int sec = col >> 9, e = col & 511, h = e >> 6, d = e & 63;
                    float* dst = (sec == 0) ? Cr : ((sec == 1) ? Ck : Cv);
                    int tt = r >> 3, bb2 = r & 7;
                    long long o = (((long long)(bb2 * 8 + h)) * 1024 + tt) * 64 + d;
                    *(float2*)(dst + o) = vr;
                    *(float2*)(dst + o + RIH) = vi;
                } else {  // EPI == 2
                    int bb2 = (int)blockIdx.z >> 3, hh = (int)blockIdx.z & 7;
                    long long o = ((long long)r * 8 + bb2) * 512 + hh * 64 + colL;
                    *(float2*)(Cr + o) = vr;
                    *(float2*)(Ci + o) = vi;
                }
            }
        }
    }
#undef LDG_TILE
#undef STS_PAIRS
#undef STS_TILE
}

// Fused softmax (in place) + head-average.  One block per (t, b, ri); loops h=0..7.
__global__ __launch_bounds__(128)
void softmax_avg_kernel(float* __restrict__ s, float* __restrict__ avg)
{
    const int t  = blockIdx.x;
    const int b  = blockIdx.y;
    const int ri = blockIdx.z;
    const int tid = threadIdx.x;
    const int w = tid >> 5;
    __shared__ float redm[4];
    __shared__ float reds[4];

    float4 acc0 = make_float4(0.f, 0.f, 0.f, 0.f);
    float4 acc1 = make_float4(0.f, 0.f, 0.f, 0.f);

    for (int h = 0; h < 8; h++) {
        float4* p4 = (float4*)(s + (((long long)ri * 64 + b * 8 + h) * 1024 + t) * 1024);
        float4 v0 = p4[tid];
        float4 v1 = p4[tid + 128];
        float mx = fmaxf(fmaxf(fmaxf(v0.x, v0.y), fmaxf(v0.z, v0.w)),
                         fmaxf(fmaxf(v1.x, v1.y), fmaxf(v1.z, v1.w)));
        #pragma unroll
        for (int o = 16; o > 0; o >>= 1)
            mx = fmaxf(mx, __shfl_xor_sync(0xffffffffu, mx, o));
        if ((tid & 31) == 0) redm[w] = mx;
        __syncthreads();
        mx = fmaxf(fmaxf(redm[0], redm[1]), fmaxf(redm[2], redm[3]));

        float e[8];
        e[0] = __expf(v0.x - mx); e[1] = __expf(v0.y - mx);
        e[2] = __expf(v0.z - mx); e[3] = __expf(v0.w - mx);
        e[4] = __expf(v1.x - mx); e[5] = __expf(v1.y - mx);
        e[6] = __expf(v1.z - mx); e[7] = __expf(v1.w - mx);
        float sum = ((e[0] + e[1]) + (e[2] + e[3])) + ((e[4] + e[5]) + (e[6] + e[7]));
        #pragma unroll
        for (int o = 16; o > 0; o >>= 1)
            sum += __shfl_xor_sync(0xffffffffu, sum, o);
        if ((tid & 31) == 0) reds[w] = sum;
        __syncthreads();
        sum = (reds[0] + reds[1]) + (reds[2] + reds[3]);
        float inv = 1.0f / sum;

        v0.x = e[0] * inv; v0.y = e[1] * inv; v0.z = e[2] * inv; v0.w = e[3] * inv;
        v1.x = e[4] * inv; v1.y = e[5] * inv; v1.z = e[6] * inv; v1.w = e[7] * inv;
        p4[tid] = v0;
        p4[tid + 128] = v1;
        acc0.x += v0.x; acc0.y += v0.y; acc0.z += v0.z; acc0.w += v0.w;
        acc1.x += v1.x; acc1.y += v1.y; acc1.z += v1.z; acc1.w += v1.w;
        __syncthreads();
    }

    float4* o4 = (float4*)(avg + (((long long)ri * 8 + b) * 1024 + t) * 1024);
    acc0.x *= 0.125f; acc0.y *= 0.125f; acc0.z *= 0.125f; acc0.w *= 0.125f;
    acc1.x *= 0.125f; acc1.y *= 0.125f; acc1.z *= 0.125f; acc1.w *= 0.125f;
    o4[tid] = acc0;
    o4[tid + 128] = acc1;
}

extern "C" void kernel_launch(void* const* d_in, const int* in_sizes, int n_in,
                              void* d_out, int out_size)
{
    const float* xr   = (const float*)d_in[0];
    const float* xi   = (const float*)d_in[1];
    const float* Wqr  = (const float*)d_in[2];
    const float* Wqi  = (const float*)d_in[3];
    const float* bqr  = (const float*)d_in[4];
    const float* bqi  = (const float*)d_in[5];
    const float* Wor  = (const float*)d_in[6];
    const float* Woi  = (const float*)d_in[7];
    const float* bor_ = (const float*)d_in[8];
    const float* boi  = (const float*)d_in[9];
    float* out = (float*)d_out;

    float *q, *k, *v, *s, *att2;
    cudaGetSymbolAddress((void**)&q, g_q);
    cudaGetSymbolAddress((void**)&k, g_k);
    cudaGetSymbolAddress((void**)&v, g_v);
    cudaGetSymbolAddress((void**)&s, g_s);
    cudaGetSymbolAddress((void**)&att2, g_att2);

    const int SMEM_STD = (4 * 128 * 24 + 4 * 64 * 24) * 4;   // 73728 B
    const int SMEM_BT  = (4 * 128 * 24 + 4 * 16 * 72) * 4;   // 67584 B

    cudaFuncSetAttribute(gemm_cplx_mma<-1, 1, true, 1, false>,
                         cudaFuncAttributeMaxDynamicSharedMemorySize, SMEM_STD);
    cudaFuncSetAttribute(gemm_cplx_mma<1, -1, false, 0, false>,
                         cudaFuncAttributeMaxDynamicSharedMemorySize, SMEM_STD);
    cudaFuncSetAttribute(gemm_cplx_mma<1, -1, false, 2, true>,
                         cudaFuncAttributeMaxDynamicSharedMemorySize, SMEM_BT);
    cudaFuncSetAttribute(gemm_cplx_mma<-1, 1, true, 0, false>,
                         cudaFuncAttributeMaxDynamicSharedMemorySize, SMEM_STD);

    // 1) QKV projection, epilogue writes q/k/v directly in head layout
    gemm_cplx_mma<-1, 1, true, 1, false><<<dim3(24, 64, 1), 256, SMEM_STD>>>(
        xr, xi, Wqr, Wqi, bqr, bqi, q, nullptr, k, v, 1536, 512, 1.0f, 0, 0, 0);

    // 2) scores (batched over 64 heads)
    gemm_cplx_mma<1, -1, false, 0, false><<<dim3(16, 8, 64), 256, SMEM_STD>>>(
        q, q + RIH, k, k + RIH, nullptr, nullptr, s, s + RIS, nullptr, nullptr,
        1024, 64, SCALE_F, 1024LL * 64, 1024LL * 64, 1024LL * 1024);

    // 3) fused softmax (in place) + head-average into d_out tail
    softmax_avg_kernel<<<dim3(1024, 8, 2), 128>>>(s, out + 2 * RIO);

    // 4) PV (batched), v consumed in natural [s][d] layout, epilogue writes [T,B,E]
    gemm_cplx_mma<1, -1, false, 2, true><<<dim3(1, 8, 64), 256, SMEM_BT>>>(
        s, s + RIS, v, v + RIH, nullptr, nullptr, att2, att2 + RIO, nullptr, nullptr,
        64, 1024, 1.0f, 1024LL * 1024, 1024LL * 64, 0);

    // 5) output projection into d_out head
    gemm_cplx_mma<-1, 1, true, 0, false><<<dim3(8, 64, 1), 256, SMEM_STD>>>(
        att2, att2 + RIO, Wor, Woi, bor_, boi, out, out + RIO, nullptr, nullptr,
        512, 512, 1.0f, 0, 0, 0);
}

// round 5
// speedup vs baseline: 1.1787x; 1.1787x over previous
#include <cuda_runtime.h>
#include <stdint.h>

#define SCALE_F 0.125f

__device__ float g_y[2ull * 8192 * 1536];
__device__ float g_q[2ull * 64 * 1024 * 64];
__device__ float g_k[2ull * 64 * 1024 * 64];
__device__ float g_vT[2ull * 64 * 64 * 1024];
__device__ float g_s[2ull * 64 * 1024 * 1024];
__device__ float g_att2[2ull * 8192 * 512];
__device__ float g_m[2ull * 64 * 1024];
__device__ float g_z[2ull * 64 * 1024];

#define RIY (8192LL * 1536)
#define RIH (64LL * 1024 * 64)
#define RIS (64LL * 1024 * 1024)
#define RIO (8192LL * 512)

__device__ __forceinline__ uint32_t f2tf32(float f) {
    uint32_t u;
    asm("cvt.rna.tf32.f32 %0, %1;" : "=r"(u) : "f"(f));
    return u;
}

#define MMA_TF32(C, A, B) \
    asm volatile("mma.sync.aligned.m16n8k8.row.col.f32.tf32.tf32.f32 " \
                 "{%0,%1,%2,%3},{%4,%5,%6,%7},{%8,%9},{%0,%1,%2,%3};" \
                 : "+f"((C)[0]), "+f"((C)[1]), "+f"((C)[2]), "+f"((C)[3]) \
                 : "r"((A)[0]), "r"((A)[1]), "r"((A)[2]), "r"((A)[3]), \
                   "r"((B)[0]), "r"((B)[1]))

// Complex GEMM on tf32 tensor cores (round-2 engine).
// C_r = alpha*(Ar.Br^T + S1*Ai.Bi^T)(+b_r) ; C_i = alpha*(Ai.Br^T + S2*Ar.Bi^T)(+b_i)
// A:[M][K] rm, B:[N][K] rm.
// SOFT: A elements pass through exp(x - m_row)*invZ_row (per-part stats) on load.
// EPI: 0 = row-major C[m][N] ; 2 = PV output -> [t*8+b][h*64+d], blockIdx.z = bh.
template<int S1, int S2, bool BIAS, int EPI, bool SOFT>
__global__ __launch_bounds__(256, 2)
void gemm_cplx_mma(const float* __restrict__ Ar, const float* __restrict__ Ai,
                   const float* __restrict__ Br, const float* __restrict__ Bi,
                   const float* __restrict__ bR, const float* __restrict__ bI,
                   float* __restrict__ Cr, float* __restrict__ Ci,
                   const float* __restrict__ gM, const float* __restrict__ gZ,
                   int N, int K, float alpha,
                   long long bsA, long long bsB, long long bsC)
{
    __shared__ uint32_t sAr[128 * 20];
    __shared__ uint32_t sAi[128 * 20];
    __shared__ uint32_t sBr[64 * 20];
    __shared__ uint32_t sBi[64 * 20];

    const int tid  = threadIdx.x;
    const int lane = tid & 31;
    const int wid  = tid >> 5;
    const int wm   = (wid >> 1) * 32;
    const int wn   = (wid & 1) * 32;
    const int g    = lane >> 2;
    const int t    = lane & 3;
    const int m0   = blockIdx.y * 128;
    const int n0   = blockIdx.x * 64;

    Ar += (long long)blockIdx.z * bsA;  Ai += (long long)blockIdx.z * bsA;
    Br += (long long)blockIdx.z * bsB;  Bi += (long long)blockIdx.z * bsB;
    Cr += (long long)blockIdx.z * bsC;  Ci += (long long)blockIdx.z * bsC;

    // per-thread softmax stats (A loader owns a single row = tid>>1)
    float mR = 0.f, zR = 1.f, mI = 0.f, zI = 1.f;
    if (SOFT) {
        int srow = (int)blockIdx.z * 1024 + m0 + (tid >> 1);
        mR = gM[srow];          zR = gZ[srow];
        mI = gM[65536 + srow];  zI = gZ[65536 + srow];
    }

    float cr[2][4][4];
    float ci[2][4][4];
    #pragma unroll
    for (int a = 0; a < 2; a++)
        #pragma unroll
        for (int b = 0; b < 4; b++)
            #pragma unroll
            for (int c = 0; c < 4; c++) { cr[a][b][c] = 0.f; ci[a][b][c] = 0.f; }

    for (int k0 = 0; k0 < K; k0 += 16) {
        // A tile: 128x16
        #pragma unroll
        for (int e = 0; e < 2; e++) {
            int idx = tid * 2 + e;
            int row = idx >> 2;
            int kq  = (idx & 3) * 4;
            long long off = (long long)(m0 + row) * K + k0 + kq;
            float4 v = *(const float4*)(Ar + off);
            if (SOFT) {
                v.x = __expf(v.x - mR) * zR; v.y = __expf(v.y - mR) * zR;
                v.z = __expf(v.z - mR) * zR; v.w = __expf(v.w - mR) * zR;
            }
            uint4 u;
            u.x = f2tf32(v.x); u.y = f2tf32(v.y); u.z = f2tf32(v.z); u.w = f2tf32(v.w);
            *(uint4*)(&sAr[row * 20 + kq]) = u;
            float4 w = *(const float4*)(Ai + off);
            if (SOFT) {
                w.x = __expf(w.x - mI) * zI; w.y = __expf(w.y - mI) * zI;
                w.z = __expf(w.z - mI) * zI; w.w = __expf(w.w - mI) * zI;
            }
            u.x = f2tf32(w.x); u.y = f2tf32(w.y); u.z = f2tf32(w.z); u.w = f2tf32(w.w);
            *(uint4*)(&sAi[row * 20 + kq]) = u;
        }
        // B tile: 64x16
        {
            int row = tid >> 2;
            int kq  = (tid & 3) * 4;
            long long off = (long long)(n0 + row) * K + k0 + kq;
            float4 v = *(const float4*)(Br + off);
            uint4 u;
            u.x = f2tf32(v.x); u.y = f2tf32(v.y); u.z = f2tf32(v.z); u.w = f2tf32(v.w);
            *(uint4*)(&sBr[row * 20 + kq]) = u;
            float4 w = *(const float4*)(Bi + off);
            u.x = f2tf32(w.x); u.y = f2tf32(w.y); u.z = f2tf32(w.z); u.w = f2tf32(w.w);
            *(uint4*)(&sBi[row * 20 + kq]) = u;
        }
        __syncthreads();

        #pragma unroll
        for (int kk = 0; kk < 16; kk += 8) {
            uint32_t far[2][4], fai[2][4], fbr[4][2], fbi[4][2];
            #pragma unroll
            for (int mt = 0; mt < 2; mt++) {
                int base = (wm + mt * 16 + g) * 20 + kk + t;
                far[mt][0] = sAr[base];
                far[mt][1] = sAr[base + 8 * 20];
                far[mt][2] = sAr[base + 4];
                far[mt][3] = sAr[base + 8 * 20 + 4];
                fai[mt][0] = sAi[base];
                fai[mt][1] = sAi[base + 8 * 20];
                fai[mt][2] = sAi[base + 4];
                fai[mt][3] = sAi[base + 8 * 20 + 4];
            }
            #pragma unroll
            for (int nt = 0; nt < 4; nt++) {
                int nb = (wn + nt * 8 + g) * 20 + kk + t;
                fbr[nt][0] = sBr[nb];
                fbr[nt][1] = sBr[nb + 4];
                fbi[nt][0] = sBi[nb];
                fbi[nt][1] = sBi[nb + 4];
            }
            #pragma unroll
            for (int mt = 0; mt < 2; mt++)
                #pragma unroll
                for (int nt = 0; nt < 4; nt++) {
                    MMA_TF32(cr[mt][nt], far[mt], fbr[nt]);
                    MMA_TF32(ci[mt][nt], fai[mt], fbr[nt]);
                }
            if (S2 > 0) {
                #pragma unroll
                for (int mt = 0; mt < 2; mt++)
                    #pragma unroll
                    for (int nt = 0; nt < 4; nt++)
                        MMA_TF32(ci[mt][nt], far[mt], fbi[nt]);
            } else {
                #pragma unroll
                for (int mt = 0; mt < 2; mt++)
                    #pragma unroll
                    for (int nt = 0; nt < 4; nt++)
                        MMA_TF32(cr[mt][nt], fai[mt], fbi[nt]);
            }
            #pragma unroll
            for (int nt = 0; nt < 4; nt++) {
                fbi[nt][0] ^= 0x80000000u;
                fbi[nt][1] ^= 0x80000000u;
            }
            if (S2 > 0) {
                #pragma unroll
                for (int mt = 0; mt < 2; mt++)
                    #pragma unroll
                    for (int nt = 0; nt < 4; nt++)
                        MMA_TF32(cr[mt][nt], fai[mt], fbi[nt]);
            } else {
                #pragma unroll
                for (int mt = 0; mt < 2; mt++)
                    #pragma unroll
                    for (int nt = 0; nt < 4; nt++)
                        MMA_TF32(ci[mt][nt], far[mt], fbi[nt]);
            }
        }
        __syncthreads();
    }

    #pragma unroll
    for (int mt = 0; mt < 2; mt++) {
        #pragma unroll
        for (int nt = 0; nt < 4; nt++) {
            const int colL = wn + nt * 8 + 2 * t;
            float br0 = 0.f, br1 = 0.f, bi0 = 0.f, bi1 = 0.f;
            if (BIAS) {
                int col = n0 + colL;
                br0 = bR[col]; br1 = bR[col + 1];
                bi0 = bI[col]; bi1 = bI[col + 1];
            }
            #pragma unroll
            for (int rh = 0; rh < 2; rh++) {
                const int r = m0 + wm + mt * 16 + g + rh * 8;
                float2 vr, vi;
                vr.x = cr[mt][nt][rh * 2 + 0] * alpha + br0;
                vr.y = cr[mt][nt][rh * 2 + 1] * alpha + br1;
                vi.x = ci[mt][nt][rh * 2 + 0] * alpha + bi0;
                vi.y = ci[mt][nt][rh * 2 + 1] * alpha + bi1;
                if (EPI == 0) {
                    long long o = (long long)r * N + n0 + colL;
                    *(float2*)(Cr + o) = vr;
                    *(float2*)(Ci + o) = vi;
                } else {  // EPI == 2: [t*8+b][h*64+d]
                    int bb2 = (int)blockIdx.z >> 3, hh = (int)blockIdx.z & 7;
                    long long o = ((long long)r * 8 + bb2) * 512 + hh * 64 + n0 + colL;
                    *(float2*)(Cr + o) = vr;
                    *(float2*)(Ci + o) = vi;
                }
            }
        }
    }
}

__global__ __launch_bounds__(256)
void reshape_qk_kernel(const float* __restrict__ y, float* __restrict__ q, float* __restrict__ k)
{
    long long idx = (long long)blockIdx.x * 256 + threadIdx.x;   // < 2^24
    int n       = (int)(idx & 1023);
    long long m = (idx >> 10) & 8191;
    int ri      = (int)(idx >> 23);
    float val = y[(long long)ri * RIY + m * 1536 + n];
    int t = (int)(m >> 3), b = (int)(m & 7);
    int sec = n >> 9, e = n & 511;
    int h = e >> 6, d = e & 63;
    long long dst = (((long long)ri * 64 + b * 8 + h) * 1024 + t) * 64 + d;
    (sec ? k : q)[dst] = val;
}

__global__ void transpose_v_kernel(const float* __restrict__ y, float* __restrict__ vT)
{
    __shared__ float tile[32][33];
    int zb = blockIdx.z;
    int ri = zb >> 6, bh = zb & 63;
    int b = bh >> 3, h = bh & 7;
    int t0 = blockIdx.x * 32, d0 = blockIdx.y * 32;
    const float* src = y + (long long)ri * RIY + 1024 + (long long)h * 64 + d0;
    #pragma unroll
    for (int r = 0; r < 32; r += 8) {
        int tloc = threadIdx.y + r;
        long long m = (long long)(t0 + tloc) * 8 + b;
        tile[tloc][threadIdx.x] = src[m * 1536 + threadIdx.x];
    }
    __syncthreads();
    float* dst = vT + (((long long)ri * 64 + bh) * 64 + d0) * 1024 + t0;
    #pragma unroll
    for (int r = 0; r < 32; r += 8) {
        int d = threadIdx.y + r;
        dst[(long long)d * 1024 + threadIdx.x] = tile[threadIdx.x][d];
    }
}

// Reads raw scores once; writes per-row (max, invZ) stats and the head-averaged
// attention weights. No normalized writeback (PV re-applies exp on load).
__global__ __launch_bounds__(128)
void stats_avg_kernel(const float* __restrict__ s, float* __restrict__ avg,
                      float* __restrict__ gm, float* __restrict__ gz)
{
    const int t  = blockIdx.x;
    const int b  = blockIdx.y;
    const int ri = blockIdx.z;
    const int tid = threadIdx.x;
    const int w = tid >> 5;
    __shared__ float redm[4];
    __shared__ float reds[4];

    float4 acc0 = make_float4(0.f, 0.f, 0.f, 0.f);
    float4 acc1 = make_float4(0.f, 0.f, 0.f, 0.f);

    for (int h = 0; h < 8; h++) {
        const float4* p4 = (const float4*)(s + (((long long)ri * 64 + b * 8 + h) * 1024 + t) * 1024);
        float4 v0 = p4[tid];
        float4 v1 = p4[tid + 128];
        float mx = fmaxf(fmaxf(fmaxf(v0.x, v0.y), fmaxf(v0.z, v0.w)),
                         fmaxf(fmaxf(v1.x, v1.y), fmaxf(v1.z, v1.w)));
        #pragma unroll
        for (int o = 16; o > 0; o >>= 1)
            mx = fmaxf(mx, __shfl_xor_sync(0xffffffffu, mx, o));
        if ((tid & 31) == 0) redm[w] = mx;
        __syncthreads();
        mx = fmaxf(fmaxf(redm[0], redm[1]), fmaxf(redm[2], redm[3]));

        float e[8];
        e[0] = __expf(v0.x - mx); e[1] = __expf(v0.y - mx);
        e[2] = __expf(v0.z - mx); e[3] = __expf(v0.w - mx);
        e[4] = __expf(v1.x - mx); e[5] = __expf(v1.y - mx);
        e[6] = __expf(v1.z - mx); e[7] = __expf(v1.w - mx);
        float sum = ((e[0] + e[1]) + (e[2] + e[3])) + ((e[4] + e[5]) + (e[6] + e[7]));
        #pragma unroll
        for (int o = 16; o > 0; o >>= 1)
            sum += __shfl_xor_sync(0xffffffffu, sum, o);
        if ((tid & 31) == 0) reds[w] = sum;
        __syncthreads();
        sum = (reds[0] + reds[1]) + (reds[2] + reds[3]);
        float inv = 1.0f / sum;

        if (tid == 0) {
            int row = ri * 65536 + (b * 8 + h) * 1024 + t;
            gm[row] = mx;
            gz[row] = inv;
        }

        acc0.x += e[0] * inv; acc0.y += e[1] * inv; acc0.z += e[2] * inv; acc0.w += e[3] * inv;
        acc1.x += e[4] * inv; acc1.y += e[5] * inv; acc1.z += e[6] * inv; acc1.w += e[7] * inv;
        __syncthreads();
    }

    float4* o4 = (float4*)(avg + (((long long)ri * 8 + b) * 1024 + t) * 1024);
    acc0.x *= 0.125f; acc0.y *= 0.125f; acc0.z *= 0.125f; acc0.w *= 0.125f;
    acc1.x *= 0.125f; acc1.y *= 0.125f; acc1.z *= 0.125f; acc1.w *= 0.125f;
    o4[tid] = acc0;
    o4[tid + 128] = acc1;
}

extern "C" void kernel_launch(void* const* d_in, const int* in_sizes, int n_in,
                              void* d_out, int out_size)
{
    const float* xr   = (const float*)d_in[0];
    const float* xi   = (const float*)d_in[1];
    const float* Wqr  = (const float*)d_in[2];
    const float* Wqi  = (const float*)d_in[3];
    const float* bqr  = (const float*)d_in[4];
    const float* bqi  = (const float*)d_in[5];
    const float* Wor  = (const float*)d_in[6];
    const float* Woi  = (const float*)d_in[7];
    const float* bor_ = (const float*)d_in[8];
    const float* boi  = (const float*)d_in[9];
    float* out = (float*)d_out;

    float *y, *q, *k, *vT, *s, *att2, *sm, *sz;
    cudaGetSymbolAddress((void**)&y, g_y);
    cudaGetSymbolAddress((void**)&q, g_q);
    cudaGetSymbolAddress((void**)&k, g_k);
    cudaGetSymbolAddress((void**)&vT, g_vT);
    cudaGetSymbolAddress((void**)&s, g_s);
    cudaGetSymbolAddress((void**)&att2, g_att2);
    cudaGetSymbolAddress((void**)&sm, g_m);
    cudaGetSymbolAddress((void**)&sz, g_z);

    // 1) QKV complex projection (row-major epilogue, known-coalesced)
    gemm_cplx_mma<-1, 1, true, 0, false><<<dim3(24, 64, 1), 256>>>(
        xr, xi, Wqr, Wqi, bqr, bqi, y, y + RIY, nullptr, nullptr,
        1536, 512, 1.0f, 0, 0, 0);

    // 2) head-layout reshapes
    reshape_qk_kernel<<<65536, 256>>>(y, q, k);
    transpose_v_kernel<<<dim3(32, 2, 128), dim3(32, 8)>>>(y, vT);

    // 3) raw scores (batched over 64 heads)
    gemm_cplx_mma<1, -1, false, 0, false><<<dim3(16, 8, 64), 256>>>(
        q, q + RIH, k, k + RIH, nullptr, nullptr, s, s + RIS, nullptr, nullptr,
        1024, 64, SCALE_F, 1024LL * 64, 1024LL * 64, 1024LL * 1024);

    // 4) stats (max, invZ) + head-averaged aw into d_out tail; no writeback
    stats_avg_kernel<<<dim3(1024, 8, 2), 128>>>(s, out + 2 * RIO, sm, sz);

    // 5) PV: softmax applied on A-load, epilogue writes [T,B,E] directly
    gemm_cplx_mma<1, -1, false, 2, true><<<dim3(1, 8, 64), 256>>>(
        s, s + RIS, vT, vT + RIH, nullptr, nullptr, att2, att2 + RIO, sm, sz,
        64, 1024, 1.0f, 1024LL * 1024, 64LL * 1024, 0);

    // 6) output projection into d_out head
    gemm_cplx_mma<-1, 1, true, 0, false><<<dim3(8, 64, 1), 256>>>(
        att2, att2 + RIO, Wor, Woi, bor_, boi, out, out + RIO, nullptr, nullptr,
        512, 512, 1.0f, 0, 0, 0);
}

// round 7
// speedup vs baseline: 1.3031x; 1.1056x over previous
#include <cuda_runtime.h>
#include <stdint.h>

#define SCALE_F 0.125f

__device__ float g_y[2ull * 8192 * 1536];
__device__ float g_q[2ull * 64 * 1024 * 64];
__device__ float g_k[2ull * 64 * 1024 * 64];
__device__ float g_vT[2ull * 64 * 64 * 1024];
__device__ float g_s[2ull * 64 * 1024 * 1024];
__device__ float g_att2[2ull * 8192 * 512];
__device__ float g_x[2ull * 8192 * 512];
__device__ float g_wq[2ull * 1536 * 512];
__device__ float g_wo[2ull * 512 * 512];

#define RIY (8192LL * 1536)
#define RIH (64LL * 1024 * 64)
#define RIS (64LL * 1024 * 1024)
#define RIO (8192LL * 512)
#define RIX (8192LL * 512)
#define RIWQ (1536LL * 512)
#define RIWO (512LL * 512)

__device__ __forceinline__ uint32_t f2tf32(float f) {
    uint32_t u;
    asm("cvt.rna.tf32.f32 %0, %1;" : "=r"(u) : "f"(f));
    return u;
}
__device__ __forceinline__ float rtf(float f) { return __uint_as_float(f2tf32(f)); }

__device__ __forceinline__ void cp16(uint32_t dst, const void* src) {
    asm volatile("cp.async.cg.shared.global [%0], [%1], 16;" :: "r"(dst), "l"(src) : "memory");
}
__device__ __forceinline__ void cpcommit() {
    asm volatile("cp.async.commit_group;" ::: "memory");
}
template<int N> __device__ __forceinline__ void cpwait() {
    asm volatile("cp.async.wait_group %0;" :: "n"(N) : "memory");
}

#define MMA_TF32(C, A, B) \
    asm volatile("mma.sync.aligned.m16n8k8.row.col.f32.tf32.tf32.f32 " \
                 "{%0,%1,%2,%3},{%4,%5,%6,%7},{%8,%9},{%0,%1,%2,%3};" \
                 : "+f"((C)[0]), "+f"((C)[1]), "+f"((C)[2]), "+f"((C)[3]) \
                 : "r"((A)[0]), "r"((A)[1]), "r"((A)[2]), "r"((A)[3]), \
                   "r"((B)[0]), "r"((B)[1]))

// Complex GEMM, tf32 tensor cores, cp.async 3-stage pipeline.
// All operands must already be tf32-valued fp32 (producer-rounded).
// C_r = alpha*(Ar.Br^T + S1*Ai.Bi^T)(+b_r) ; C_i = alpha*(Ai.Br^T + S2*Ar.Bi^T)(+b_i)
// A:[M][K] rm, B:[N][K] rm. BM=128, BN=64, BK=16.
// EPI: 0 = row-major C[m][N] (raw fp32) ; 2 = [t*8+b][h*64+d], tf32-rounded stores.
template<int S1, int S2, bool BIAS, int EPI>
__global__ __launch_bounds__(256, 2)
void gemm_cplx_pipe(const float* __restrict__ Ar, const float* __restrict__ Ai,
                    const float* __restrict__ Br, const float* __restrict__ Bi,
                    const float* __restrict__ bR, const float* __restrict__ bI,
                    float* __restrict__ Cr, float* __restrict__ Ci,
                    int N, int K, float alpha,
                    long long bsA, long long bsB, long long bsC)
{
    extern __shared__ uint32_t sm[];
    const int STG = 7680;   // words per stage: A 2*2560 + B 2*1280
    // stage offsets: Ar=0, Ai=2560, Br=5120, Bi=6400  (row stride 20 words)

    const int tid  = threadIdx.x;
    const int lane = tid & 31;
    const int wid  = tid >> 5;
    const int wm   = (wid >> 1) * 32;
    const int wn   = (wid & 1) * 32;
    const int g    = lane >> 2;
    const int t    = lane & 3;
    const int m0   = blockIdx.y * 128;
    const int n0   = blockIdx.x * 64;

    Ar += (long long)blockIdx.z * bsA;  Ai += (long long)blockIdx.z * bsA;
    Br += (long long)blockIdx.z * bsB;  Bi += (long long)blockIdx.z * bsB;
    Cr += (long long)blockIdx.z * bsC;  Ci += (long long)blockIdx.z * bsC;

    // loader mapping
    const int arow = tid >> 1, akq = (tid & 1) * 8;
    const int brow = tid >> 2, bkq = (tid & 3) * 4;
    const float* gAr = Ar + (long long)(m0 + arow) * K + akq;
    const float* gAi = Ai + (long long)(m0 + arow) * K + akq;
    const float* gBr = Br + (long long)(n0 + brow) * K + bkq;
    const float* gBi = Bi + (long long)(n0 + brow) * K + bkq;
    const uint32_t sbase = (uint32_t)__cvta_generic_to_shared(sm);
    const uint32_t adst = sbase + (arow * 20 + akq) * 4;
    const uint32_t bdst = sbase + (brow * 20 + bkq) * 4;

    float cr[2][4][4];
    float ci[2][4][4];
    #pragma unroll
    for (int a = 0; a < 2; a++)
        #pragma unroll
        for (int b = 0; b < 4; b++)
            #pragma unroll
            for (int c = 0; c < 4; c++) { cr[a][b][c] = 0.f; ci[a][b][c] = 0.f; }

#define ISSUE(STAGE, K0) do {                                                  \
    uint32_t st = (uint32_t)(((STAGE) % 3) * STG * 4);                         \
    cp16(adst + st,                 gAr + (K0));                               \
    cp16(adst + st + 16,            gAr + (K0) + 4);                           \
    cp16(adst + st + 2560 * 4,      gAi + (K0));                               \
    cp16(adst + st + 2560 * 4 + 16, gAi + (K0) + 4);                           \
    cp16(bdst + st + 5120 * 4,      gBr + (K0));                               \
    cp16(bdst + st + 6400 * 4,      gBi + (K0));                               \
    cpcommit();                                                                \
} while (0)

    const int nk = K / 16;
    ISSUE(0, 0);
    ISSUE(1, 16);

    for (int it = 0; it < nk; it++) {
        if (it + 2 < nk) cpwait<1>(); else cpwait<0>();
        __syncthreads();
        if (it + 2 < nk) ISSUE(it + 2, (it + 2) * 16);

        const uint32_t* sp = sm + (it % 3) * STG;
        const uint32_t* spA = sp;
        const uint32_t* spAi = sp + 2560;
        const uint32_t* spB = sp + 5120;
        const uint32_t* spBi = sp + 6400;

        #pragma unroll
        for (int kk = 0; kk < 16; kk += 8) {
            uint32_t far[2][4], fai[2][4], fbr[4][2], fbi[4][2];
            #pragma unroll
            for (int mt = 0; mt < 2; mt++) {
                int base = (wm + mt * 16 + g) * 20 + kk + t;
                far[mt][0] = spA[base];
                far[mt][1] = spA[base + 8 * 20];
                far[mt][2] = spA[base + 4];
                far[mt][3] = spA[base + 8 * 20 + 4];
                fai[mt][0] = spAi[base];
                fai[mt][1] = spAi[base + 8 * 20];
                fai[mt][2] = spAi[base + 4];
                fai[mt][3] = spAi[base + 8 * 20 + 4];
            }
            #pragma unroll
            for (int nt = 0; nt < 4; nt++) {
                int nb = (wn + nt * 8 + g) * 20 + kk + t;
                fbr[nt][0] = spB[nb];
                fbr[nt][1] = spB[nb + 4];
                fbi[nt][0] = spBi[nb];
                fbi[nt][1] = spBi[nb + 4];
            }
            #pragma unroll
            for (int mt = 0; mt < 2; mt++)
                #pragma unroll
                for (int nt = 0; nt < 4; nt++) {
                    MMA_TF32(cr[mt][nt], far[mt], fbr[nt]);
                    MMA_TF32(ci[mt][nt], fai[mt], fbr[nt]);
                }
            if (S2 > 0) {
                #pragma unroll
                for (int mt = 0; mt < 2; mt++)
                    #pragma unroll
                    for (int nt = 0; nt < 4; nt++)
                        MMA_TF32(ci[mt][nt], far[mt], fbi[nt]);
            } else {
                #pragma unroll
                for (int mt = 0; mt < 2; mt++)
                    #pragma unroll
                    for (int nt = 0; nt < 4; nt++)
                        MMA_TF32(cr[mt][nt], fai[mt], fbi[nt]);
            }
            #pragma unroll
            for (int nt = 0; nt < 4; nt++) {
                fbi[nt][0] ^= 0x80000000u;
                fbi[nt][1] ^= 0x80000000u;
            }
            if (S2 > 0) {
                #pragma unroll
                for (int mt = 0; mt < 2; mt++)
                    #pragma unroll
                    for (int nt = 0; nt < 4; nt++)
                        MMA_TF32(cr[mt][nt], fai[mt], fbi[nt]);
            } else {
                #pragma unroll
                for (int mt = 0; mt < 2; mt++)
                    #pragma unroll
                    for (int nt = 0; nt < 4; nt++)
                        MMA_TF32(ci[mt][nt], far[mt], fbi[nt]);
            }
        }
    }
#undef ISSUE

    #pragma unroll
    for (int mt = 0; mt < 2; mt++) {
        #pragma unroll
        for (int nt = 0; nt < 4; nt++) {
            const int colL = wn + nt * 8 + 2 * t;
            float br0 = 0.f, br1 = 0.f, bi0 = 0.f, bi1 = 0.f;
            if (BIAS) {
                int col = n0 + colL;
                br0 = bR[col]; br1 = bR[col + 1];
                bi0 = bI[col]; bi1 = bI[col + 1];
            }
            #pragma unroll
            for (int rh = 0; rh < 2; rh++) {
                const int r = m0 + wm + mt * 16 + g + rh * 8;
                float2 vr, vi;
                vr.x = cr[mt][nt][rh * 2 + 0] * alpha + br0;
                vr.y = cr[mt][nt][rh * 2 + 1] * alpha + br1;
                vi.x = ci[mt][nt][rh * 2 + 0] * alpha + bi0;
                vi.y = ci[mt][nt][rh * 2 + 1] * alpha + bi1;
                if (EPI == 0) {
                    long long o = (long long)r * N + n0 + colL;
                    *(float2*)(Cr + o) = vr;
                    *(float2*)(Ci + o) = vi;
                } else {  // EPI == 2: PV output, tf32-rounded for the next GEMM
                    vr.x = rtf(vr.x); vr.y = rtf(vr.y);
                    vi.x = rtf(vi.x); vi.y = rtf(vi.y);
                    int bb2 = (int)blockIdx.z >> 3, hh = (int)blockIdx.z & 7;
                    long long o = ((long long)r * 8 + bb2) * 512 + hh * 64 + n0 + colL;
                    *(float2*)(Cr + o) = vr;
                    *(float2*)(Ci + o) = vi;
                }
            }
        }
    }
}

__global__ __launch_bounds__(256)
void round_copy_kernel(const float4* __restrict__ src, float4* __restrict__ dst, int n4)
{
    int i = blockIdx.x * 256 + threadIdx.x;
    if (i < n4) {
        float4 v = src[i];
        uint4 u;
        u.x = f2tf32(v.x); u.y = f2tf32(v.y); u.z = f2tf32(v.z); u.w = f2tf32(v.w);
        *(uint4*)(dst + i) = u;
    }
}

__global__ __launch_bounds__(256)
void reshape_qk_kernel(const float* __restrict__ y, float* __restrict__ q, float* __restrict__ k)
{
    long long idx = (long long)blockIdx.x * 256 + threadIdx.x;   // < 2^24
    int n       = (int)(idx & 1023);
    long long m = (idx >> 10) & 8191;
    int ri      = (int)(idx >> 23);
    float val = rtf(y[(long long)ri * RIY + m * 1536 + n]);
    int t = (int)(m >> 3), b = (int)(m & 7);
    int sec = n >> 9, e = n & 511;
    int h = e >> 6, d = e & 63;
    long long dst = (((long long)ri * 64 + b * 8 + h) * 1024 + t) * 64 + d;
    (sec ? k : q)[dst] = val;
}

__global__ void transpose_v_kernel(const float* __restrict__ y, float* __restrict__ vT)
{
    __shared__ float tile[32][33];
    int zb = blockIdx.z;
    int ri = zb >> 6, bh = zb & 63;
    int b = bh >> 3, h = bh & 7;
    int t0 = blockIdx.x * 32, d0 = blockIdx.y * 32;
    const float* src = y + (long long)ri * RIY + 1024 + (long long)h * 64 + d0;
    #pragma unroll
    for (int r = 0; r < 32; r += 8) {
        int tloc = threadIdx.y + r;
        long long m = (long long)(t0 + tloc) * 8 + b;
        tile[tloc][threadIdx.x] = src[m * 1536 + threadIdx.x];
    }
    __syncthreads();
    float* dst = vT + (((long long)ri * 64 + bh) * 64 + d0) * 1024 + t0;
    #pragma unroll
    for (int r = 0; r < 32; r += 8) {
        int d = threadIdx.y + r;
        dst[(long long)d * 1024 + threadIdx.x] = rtf(tile[threadIdx.x][d]);
    }
}

// Reads raw scores; writes normalized aw back in place (tf32-rounded, ready for
// cp.async PV) and the head-averaged aw (full fp32) into the output tail.
__global__ __launch_bounds__(128)
void stats_avg_kernel(float* __restrict__ s, float* __restrict__ avg)
{
    const int t  = blockIdx.x;
    const int b  = blockIdx.y;
    const int ri = blockIdx.z;
    const int tid = threadIdx.x;
    const int w = tid >> 5;
    __shared__ float redm[4];
    __shared__ float reds[4];

    float4 acc0 = make_float4(0.f, 0.f, 0.f, 0.f);
    float4 acc1 = make_float4(0.f, 0.f, 0.f, 0.f);

    for (int h = 0; h < 8; h++) {
        float4* p4 = (float4*)(s + (((long long)ri * 64 + b * 8 + h) * 1024 + t) * 1024);
        float4 v0 = p4[tid];
        float4 v1 = p4[tid + 128];
        float mx = fmaxf(fmaxf(fmaxf(v0.x, v0.y), fmaxf(v0.z, v0.w)),
                         fmaxf(fmaxf(v1.x, v1.y), fmaxf(v1.z, v1.w)));
        #pragma unroll
        for (int o = 16; o > 0; o >>= 1)
            mx = fmaxf(mx, __shfl_xor_sync(0xffffffffu, mx, o));
        if ((tid & 31) == 0) redm[w] = mx;
        __syncthreads();
        mx = fmaxf(fmaxf(redm[0], redm[1]), fmaxf(redm[2], redm[3]));

        float e[8];
        e[0] = __expf(v0.x - mx); e[1] = __expf(v0.y - mx);
        e[2] = __expf(v0.z - mx); e[3] = __expf(v0.w - mx);
        e[4] = __expf(v1.x - mx); e[5] = __expf(v1.y - mx);
        e[6] = __expf(v1.z - mx); e[7] = __expf(v1.w - mx);
        float sum = ((e[0] + e[1]) + (e[2] + e[3])) + ((e[4] + e[5]) + (e[6] + e[7]));
        #pragma unroll
        for (int o = 16; o > 0; o >>= 1)
            sum += __shfl_xor_sync(0xffffffffu, sum, o);
        if ((tid & 31) == 0) reds[w] = sum;
        __syncthreads();
        sum = (reds[0] + reds[1]) + (reds[2] + reds[3]);
        float inv = 1.0f / sum;

        float n0x = e[0] * inv, n0y = e[1] * inv, n0z = e[2] * inv, n0w = e[3] * inv;
        float n1x = e[4] * inv, n1y = e[5] * inv, n1z = e[6] * inv, n1w = e[7] * inv;

        float4 w0, w1;
        w0.x = rtf(n0x); w0.y = rtf(n0y); w0.z = rtf(n0z); w0.w = rtf(n0w);
        w1.x = rtf(n1x); w1.y = rtf(n1y); w1.z = rtf(n1z); w1.w = rtf(n1w);
        p4[tid] = w0;
        p4[tid + 128] = w1;

        acc0.x += n0x; acc0.y += n0y; acc0.z += n0z; acc0.w += n0w;
        acc1.x += n1x; acc1.y += n1y; acc1.z += n1z; acc1.w += n1w;
        __syncthreads();
    }

    float4* o4 = (float4*)(avg + (((long long)ri * 8 + b) * 1024 + t) * 1024);
    acc0.x *= 0.125f; acc0.y *= 0.125f; acc0.z *= 0.125f; acc0.w *= 0.125f;
    acc1.x *= 0.125f; acc1.y *= 0.125f; acc1.z *= 0.125f; acc1.w *= 0.125f;
    o4[tid] = acc0;
    o4[tid + 128] = acc1;
}

extern "C" void kernel_launch(void* const* d_in, const int* in_sizes, int n_in,
                              void* d_out, int out_size)
{
    const float* xr   = (const float*)d_in[0];
    const float* xi   = (const float*)d_in[1];
    const float* Wqr  = (const float*)d_in[2];
    const float* Wqi  = (const float*)d_in[3];
    const float* bqr  = (const float*)d_in[4];
    const float* bqi  = (const float*)d_in[5];
    const float* Wor  = (const float*)d_in[6];
    const float* Woi  = (const float*)d_in[7];
    const float* bor_ = (const float*)d_in[8];
    const float* boi  = (const float*)d_in[9];
    float* out = (float*)d_out;

    float *y, *q, *k, *vT, *s, *att2, *x, *wq, *wo;
    cudaGetSymbolAddress((void**)&y, g_y);
    cudaGetSymbolAddress((void**)&q, g_q);
    cudaGetSymbolAddress((void**)&k, g_k);
    cudaGetSymbolAddress((void**)&vT, g_vT);
    cudaGetSymbolAddress((void**)&s, g_s);
    cudaGetSymbolAddress((void**)&att2, g_att2);
    cudaGetSymbolAddress((void**)&x, g_x);
    cudaGetSymbolAddress((void**)&wq, g_wq);
    cudaGetSymbolAddress((void**)&wo, g_wo);

    const int SMEM_PIPE = 3 * 7680 * 4;   // 92160 B

    cudaFuncSetAttribute(gemm_cplx_pipe<-1, 1, true, 0>,
                         cudaFuncAttributeMaxDynamicSharedMemorySize, SMEM_PIPE);
    cudaFuncSetAttribute(gemm_cplx_pipe<1, -1, false, 0>,
                         cudaFuncAttributeMaxDynamicSharedMemorySize, SMEM_PIPE);
    cudaFuncSetAttribute(gemm_cplx_pipe<1, -1, false, 2>,
                         cudaFuncAttributeMaxDynamicSharedMemorySize, SMEM_PIPE);

    // 0) tf32-round inputs and weights into scratch
    round_copy_kernel<<<4096, 256>>>((const float4*)xr, (float4*)x, 1048576);
    round_copy_kernel<<<4096, 256>>>((const float4*)xi, (float4*)(x + RIX), 1048576);
    round_copy_kernel<<<768, 256>>>((const float4*)Wqr, (float4*)wq, 196608);
    round_copy_kernel<<<768, 256>>>((const float4*)Wqi, (float4*)(wq + RIWQ), 196608);
    round_copy_kernel<<<256, 256>>>((const float4*)Wor, (float4*)wo, 65536);
    round_copy_kernel<<<256, 256>>>((const float4*)Woi, (float4*)(wo + RIWO), 65536);

    // 1) QKV complex projection
    gemm_cplx_pipe<-1, 1, true, 0><<<dim3(24, 64, 1), 256, SMEM_PIPE>>>(
        x, x + RIX, wq, wq + RIWQ, bqr, bqi, y, y + RIY,
        1536, 512, 1.0f, 0, 0, 0);

    // 2) head-layout reshapes (tf32-rounding producers)
    reshape_qk_kernel<<<65536, 256>>>(y, q, k);
    transpose_v_kernel<<<dim3(32, 2, 128), dim3(32, 8)>>>(y, vT);

    // 3) raw scores (batched over 64 heads)
    gemm_cplx_pipe<1, -1, false, 0><<<dim3(16, 8, 64), 256, SMEM_PIPE>>>(
        q, q + RIH, k, k + RIH, nullptr, nullptr, s, s + RIS,
        1024, 64, SCALE_F, 1024LL * 64, 1024LL * 64, 1024LL * 1024);

    // 4) softmax stats + normalized writeback + head-average into d_out tail
    stats_avg_kernel<<<dim3(1024, 8, 2), 128>>>(s, out + 2 * RIO);

    // 5) PV: pure GEMM on normalized aw, epilogue writes [T,B,E] (rounded)
    gemm_cplx_pipe<1, -1, false, 2><<<dim3(1, 8, 64), 256, SMEM_PIPE>>>(
        s, s + RIS, vT, vT + RIH, nullptr, nullptr, att2, att2 + RIO,
        64, 1024, 1.0f, 1024LL * 1024, 64LL * 1024, 0);

    // 6) output projection into d_out head
    gemm_cplx_pipe<-1, 1, true, 0><<<dim3(8, 64, 1), 256, SMEM_PIPE>>>(
        att2, att2 + RIO, wo, wo + RIWO, bor_, boi, out, out + RIO,
        512, 512, 1.0f, 0, 0, 0);
}

// round 8
// speedup vs baseline: 1.3372x; 1.0262x over previous
#include <cuda_runtime.h>
#include <stdint.h>

#define SCALE_F 0.125f

__device__ float g_y[2ull * 8192 * 1536];
__device__ float g_q[2ull * 64 * 1024 * 64];
__device__ float g_k[2ull * 64 * 1024 * 64];
__device__ float g_vT[2ull * 64 * 64 * 1024];
__device__ float g_s[2ull * 64 * 1024 * 1024];
__device__ float g_att2[2ull * 8192 * 512];
__device__ float g_x[2ull * 8192 * 512];
__device__ float g_wq[2ull * 1536 * 512];
__device__ float g_wo[2ull * 512 * 512];
__device__ float g_m[2ull * 64 * 1024];
__device__ float g_z[2ull * 64 * 1024];

#define RIY (8192LL * 1536)
#define RIH (64LL * 1024 * 64)
#define RIS (64LL * 1024 * 1024)
#define RIO (8192LL * 512)
#define RIX (8192LL * 512)
#define RIWQ (1536LL * 512)
#define RIWO (512LL * 512)

__device__ __forceinline__ uint32_t f2tf32(float f) {
    uint32_t u;
    asm("cvt.rna.tf32.f32 %0, %1;" : "=r"(u) : "f"(f));
    return u;
}
__device__ __forceinline__ float rtf(float f) { return __uint_as_float(f2tf32(f)); }

__device__ __forceinline__ void cp16(uint32_t dst, const void* src) {
    asm volatile("cp.async.cg.shared.global [%0], [%1], 16;" :: "r"(dst), "l"(src) : "memory");
}
__device__ __forceinline__ void cpcommit() {
    asm volatile("cp.async.commit_group;" ::: "memory");
}
template<int N> __device__ __forceinline__ void cpwait() {
    asm volatile("cp.async.wait_group %0;" :: "n"(N) : "memory");
}

#define MMA_TF32(C, A, B) \
    asm volatile("mma.sync.aligned.m16n8k8.row.col.f32.tf32.tf32.f32 " \
                 "{%0,%1,%2,%3},{%4,%5,%6,%7},{%8,%9},{%0,%1,%2,%3};" \
                 : "+f"((C)[0]), "+f"((C)[1]), "+f"((C)[2]), "+f"((C)[3]) \
                 : "r"((A)[0]), "r"((A)[1]), "r"((A)[2]), "r"((A)[3]), \
                   "r"((B)[0]), "r"((B)[1]))

// Fragment loads + 16 complex-MMA block shared by both engines.
#define COMPUTE_K8(spA, spAi, spB, spBi, kk)                                   \
do {                                                                           \
    uint32_t far[2][4], fai[2][4], fbr[4][2], fbi[4][2];                       \
    _Pragma("unroll")                                                          \
    for (int mt = 0; mt < 2; mt++) {                                           \
        int base = (wm + mt * 16 + g) * 20 + (kk) + t;                         \
        far[mt][0] = (spA)[base];                                              \
        far[mt][1] = (spA)[base + 8 * 20];                                     \
        far[mt][2] = (spA)[base + 4];                                          \
        far[mt][3] = (spA)[base + 8 * 20 + 4];                                 \
        fai[mt][0] = (spAi)[base];                                             \
        fai[mt][1] = (spAi)[base + 8 * 20];                                    \
        fai[mt][2] = (spAi)[base + 4];                                         \
        fai[mt][3] = (spAi)[base + 8 * 20 + 4];                                \
    }                                                                          \
    _Pragma("unroll")                                                          \
    for (int nt = 0; nt < 4; nt++) {                                           \
        int nb = (wn + nt * 8 + g) * 20 + (kk) + t;                            \
        fbr[nt][0] = (spB)[nb];                                                \
        fbr[nt][1] = (spB)[nb + 4];                                            \
        fbi[nt][0] = (spBi)[nb];                                               \
        fbi[nt][1] = (spBi)[nb + 4];                                           \
    }                                                                          \
    _Pragma("unroll")                                                          \
    for (int mt = 0; mt < 2; mt++)                                             \
        _Pragma("unroll")                                                      \
        for (int nt = 0; nt < 4; nt++) {                                       \
            MMA_TF32(cr[mt][nt], far[mt], fbr[nt]);                            \
            MMA_TF32(ci[mt][nt], fai[mt], fbr[nt]);                            \
        }                                                                      \
    if (S2 > 0) {                                                              \
        _Pragma("unroll")                                                      \
        for (int mt = 0; mt < 2; mt++)                                         \
            _Pragma("unroll")                                                  \
            for (int nt = 0; nt < 4; nt++)                                     \
                MMA_TF32(ci[mt][nt], far[mt], fbi[nt]);                        \
    } else {                                                                   \
        _Pragma("unroll")                                                      \
        for (int mt = 0; mt < 2; mt++)                                         \
            _Pragma("unroll")                                                  \
            for (int nt = 0; nt < 4; nt++)                                     \
                MMA_TF32(cr[mt][nt], fai[mt], fbi[nt]);                        \
    }                                                                          \
    _Pragma("unroll")                                                          \
    for (int nt = 0; nt < 4; nt++) {                                           \
        fbi[nt][0] ^= 0x80000000u;                                             \
        fbi[nt][1] ^= 0x80000000u;                                             \
    }                                                                          \
    if (S2 > 0) {                                                              \
        _Pragma("unroll")                                                      \
        for (int mt = 0; mt < 2; mt++)                                         \
            _Pragma("unroll")                                                  \
            for (int nt = 0; nt < 4; nt++)                                     \
                MMA_TF32(cr[mt][nt], fai[mt], fbi[nt]);                        \
    } else {                                                                   \
        _Pragma("unroll")                                                      \
        for (int mt = 0; mt < 2; mt++)                                         \
            _Pragma("unroll")                                                  \
            for (int nt = 0; nt < 4; nt++)                                     \
                MMA_TF32(ci[mt][nt], far[mt], fbi[nt]);                        \
    }                                                                          \
} while (0)

// ======================= main pipelined engine (unchanged from R7) =======================
template<int S1, int S2, bool BIAS, int EPI>
__global__ __launch_bounds__(256, 2)
void gemm_cplx_pipe(const float* __restrict__ Ar, const float* __restrict__ Ai,
                    const float* __restrict__ Br, const float* __restrict__ Bi,
                    const float* __restrict__ bR, const float* __restrict__ bI,
                    float* __restrict__ Cr, float* __restrict__ Ci,
                    int N, int K, float alpha,
                    long long bsA, long long bsB, long long bsC)
{
    extern __shared__ uint32_t sm[];
    const int STG = 7680;

    const int tid  = threadIdx.x;
    const int lane = tid & 31;
    const int wid  = tid >> 5;
    const int wm   = (wid >> 1) * 32;
    const int wn   = (wid & 1) * 32;
    const int g    = lane >> 2;
    const int t    = lane & 3;
    const int m0   = blockIdx.y * 128;
    const int n0   = blockIdx.x * 64;

    Ar += (long long)blockIdx.z * bsA;  Ai += (long long)blockIdx.z * bsA;
    Br += (long long)blockIdx.z * bsB;  Bi += (long long)blockIdx.z * bsB;
    Cr += (long long)blockIdx.z * bsC;  Ci += (long long)blockIdx.z * bsC;

    const int arow = tid >> 1, akq = (tid & 1) * 8;
    const int brow = tid >> 2, bkq = (tid & 3) * 4;
    const float* gAr = Ar + (long long)(m0 + arow) * K + akq;
    const float* gAi = Ai + (long long)(m0 + arow) * K + akq;
    const float* gBr = Br + (long long)(n0 + brow) * K + bkq;
    const float* gBi = Bi + (long long)(n0 + brow) * K + bkq;
    const uint32_t sbase = (uint32_t)__cvta_generic_to_shared(sm);
    const uint32_t adst = sbase + (arow * 20 + akq) * 4;
    const uint32_t bdst = sbase + (brow * 20 + bkq) * 4;

    float cr[2][4][4];
    float ci[2][4][4];
    #pragma unroll
    for (int a = 0; a < 2; a++)
        #pragma unroll
        for (int b = 0; b < 4; b++)
            #pragma unroll
            for (int c = 0; c < 4; c++) { cr[a][b][c] = 0.f; ci[a][b][c] = 0.f; }

#define ISSUE(STAGE, K0) do {                                                  \
    uint32_t st = (uint32_t)(((STAGE) % 3) * STG * 4);                         \
    cp16(adst + st,                 gAr + (K0));                               \
    cp16(adst + st + 16,            gAr + (K0) + 4);                           \
    cp16(adst + st + 2560 * 4,      gAi + (K0));                               \
    cp16(adst + st + 2560 * 4 + 16, gAi + (K0) + 4);                           \
    cp16(bdst + st + 5120 * 4,      gBr + (K0));                               \
    cp16(bdst + st + 6400 * 4,      gBi + (K0));                               \
    cpcommit();                                                                \
} while (0)

    const int nk = K / 16;
    ISSUE(0, 0);
    ISSUE(1, 16);

    for (int it = 0; it < nk; it++) {
        if (it + 2 < nk) cpwait<1>(); else cpwait<0>();
        __syncthreads();
        if (it + 2 < nk) ISSUE(it + 2, (it + 2) * 16);

        const uint32_t* sp = sm + (it % 3) * STG;
        #pragma unroll
        for (int kk = 0; kk < 16; kk += 8)
            COMPUTE_K8(sp, sp + 2560, sp + 5120, sp + 6400, kk);
    }
#undef ISSUE

    #pragma unroll
    for (int mt = 0; mt < 2; mt++) {
        #pragma unroll
        for (int nt = 0; nt < 4; nt++) {
            const int colL = wn + nt * 8 + 2 * t;
            float br0 = 0.f, br1 = 0.f, bi0 = 0.f, bi1 = 0.f;
            if (BIAS) {
                int col = n0 + colL;
                br0 = bR[col]; br1 = bR[col + 1];
                bi0 = bI[col]; bi1 = bI[col + 1];
            }
            #pragma unroll
            for (int rh = 0; rh < 2; rh++) {
                const int r = m0 + wm + mt * 16 + g + rh * 8;
                float2 vr, vi;
                vr.x = cr[mt][nt][rh * 2 + 0] * alpha + br0;
                vr.y = cr[mt][nt][rh * 2 + 1] * alpha + br1;
                vi.x = ci[mt][nt][rh * 2 + 0] * alpha + bi0;
                vi.y = ci[mt][nt][rh * 2 + 1] * alpha + bi1;
                if (EPI == 0) {
                    long long o = (long long)r * N + n0 + colL;
                    *(float2*)(Cr + o) = vr;
                    *(float2*)(Ci + o) = vi;
                } else {
                    vr.x = rtf(vr.x); vr.y = rtf(vr.y);
                    vi.x = rtf(vi.x); vi.y = rtf(vi.y);
                    int bb2 = (int)blockIdx.z >> 3, hh = (int)blockIdx.z & 7;
                    long long o = ((long long)r * 8 + bb2) * 512 + hh * 64 + n0 + colL;
                    *(float2*)(Cr + o) = vr;
                    *(float2*)(Ci + o) = vi;
                }
            }
        }
    }
}

// ======================= PV engine: softmax-on-load A, cp.async B =======================
// A = raw scores [bh][t][s]; applies exp(x-m)*invZ then tf32 on the load path.
// B = vT [bh][d=64][s], N=64, K=1024. Output EPI2 [t*8+b][h*64+d], tf32-rounded.
__global__ __launch_bounds__(256, 2)
void gemm_pv_soft(const float* __restrict__ S, const float* __restrict__ Vt,
                  const float* __restrict__ gM, const float* __restrict__ gZ,
                  float* __restrict__ Cr, float* __restrict__ Ci)
{
    constexpr int S2 = -1;   // for COMPUTE_K8
    extern __shared__ uint32_t sm[];
    // A: 2 stages x (Ar 2560 + Ai 2560); B: 3 stages x (Br 1280 + Bi 1280)
    uint32_t* sA  = sm;                 // [2][5120]
    uint32_t* sB  = sm + 10240;         // [3][2560]

    const int tid  = threadIdx.x;
    const int lane = tid & 31;
    const int wid  = tid >> 5;
    const int wm   = (wid >> 1) * 32;
    const int wn   = (wid & 1) * 32;
    const int g    = lane >> 2;
    const int t    = lane & 3;
    const int m0   = blockIdx.y * 128;
    const int bh   = blockIdx.z;

    const float* Ar = S + (long long)bh * (1024LL * 1024);
    const float* Ai = Ar + RIS;
    const float* Br = Vt + (long long)bh * (64LL * 1024);
    const float* Bi = Br + RIH;

    const int arow = tid >> 1, akq = (tid & 1) * 8;
    const int brow = tid >> 2, bkq = (tid & 3) * 4;
    const float* gAr = Ar + (long long)(m0 + arow) * 1024 + akq;
    const float* gAi = Ai + (long long)(m0 + arow) * 1024 + akq;
    const float* gBr = Br + (long long)brow * 1024 + bkq;
    const float* gBi = Bi + (long long)brow * 1024 + bkq;
    const uint32_t sbase = (uint32_t)__cvta_generic_to_shared(sm);
    const uint32_t bdst = sbase + 10240 * 4 + (brow * 20 + bkq) * 4;

    const int srow = bh * 1024 + m0 + arow;
    const float mR = gM[srow],          zR = gZ[srow];
    const float mI = gM[65536 + srow],  zI = gZ[65536 + srow];

    float4 Ar0, Ar1, Ai0, Ai1;

    float cr[2][4][4];
    float ci[2][4][4];
    #pragma unroll
    for (int a = 0; a < 2; a++)
        #pragma unroll
        for (int b = 0; b < 4; b++)
            #pragma unroll
            for (int c = 0; c < 4; c++) { cr[a][b][c] = 0.f; ci[a][b][c] = 0.f; }

#define LDGA(K0) do {                                                          \
    Ar0 = *(const float4*)(gAr + (K0));  Ar1 = *(const float4*)(gAr + (K0) + 4); \
    Ai0 = *(const float4*)(gAi + (K0));  Ai1 = *(const float4*)(gAi + (K0) + 4); \
} while (0)

#define EXPSTS(P) do {                                                         \
    uint32_t* ab = sA + (P) * 5120 + arow * 20 + akq;                          \
    uint4 u;                                                                   \
    u.x = f2tf32(__expf(Ar0.x - mR) * zR); u.y = f2tf32(__expf(Ar0.y - mR) * zR); \
    u.z = f2tf32(__expf(Ar0.z - mR) * zR); u.w = f2tf32(__expf(Ar0.w - mR) * zR); \
    *(uint4*)ab = u;                                                           \
    u.x = f2tf32(__expf(Ar1.x - mR) * zR); u.y = f2tf32(__expf(Ar1.y - mR) * zR); \
    u.z = f2tf32(__expf(Ar1.z - mR) * zR); u.w = f2tf32(__expf(Ar1.w - mR) * zR); \
    *(uint4*)(ab + 4) = u;                                                     \
    ab += 2560;                                                                \
    u.x = f2tf32(__expf(Ai0.x - mI) * zI); u.y = f2tf32(__expf(Ai0.y - mI) * zI); \
    u.z = f2tf32(__expf(Ai0.z - mI) * zI); u.w = f2tf32(__expf(Ai0.w - mI) * zI); \
    *(uint4*)ab = u;                                                           \
    u.x = f2tf32(__expf(Ai1.x - mI) * zI); u.y = f2tf32(__expf(Ai1.y - mI) * zI); \
    u.z = f2tf32(__expf(Ai1.z - mI) * zI); u.w = f2tf32(__expf(Ai1.w - mI) * zI); \
    *(uint4*)(ab + 4) = u;                                                     \
} while (0)

#define ISSUEB(STAGE, K0) do {                                                 \
    uint32_t st = (uint32_t)(((STAGE) % 3) * 2560 * 4);                        \
    cp16(bdst + st,            gBr + (K0));                                    \
    cp16(bdst + st + 1280 * 4, gBi + (K0));                                    \
    cpcommit();                                                                \
} while (0)

    const int nk = 64;   // K = 1024
    LDGA(0);
    EXPSTS(0);
    ISSUEB(0, 0);
    ISSUEB(1, 16);

    for (int it = 0; it < nk; it++) {
        if (it + 1 < nk) LDGA((it + 1) * 16);
        if (it + 2 < nk) cpwait<1>(); else cpwait<0>();
        __syncthreads();
        if (it + 2 < nk) ISSUEB(it + 2, (it + 2) * 16);

        const uint32_t* spA = sA + (it & 1) * 5120;
        const uint32_t* spB = sB + (it % 3) * 2560;
        #pragma unroll
        for (int kk = 0; kk < 16; kk += 8)
            COMPUTE_K8(spA, spA + 2560, spB, spB + 1280, kk);

        if (it + 1 < nk) {
            __syncthreads();
            EXPSTS((it + 1) & 1);
        }
    }
#undef LDGA
#undef EXPSTS
#undef ISSUEB

    #pragma unroll
    for (int mt = 0; mt < 2; mt++) {
        #pragma unroll
        for (int nt = 0; nt < 4; nt++) {
            const int colL = wn + nt * 8 + 2 * t;
            #pragma unroll
            for (int rh = 0; rh < 2; rh++) {
                const int r = m0 + wm + mt * 16 + g + rh * 8;
                float2 vr, vi;
                vr.x = rtf(cr[mt][nt][rh * 2 + 0]);
                vr.y = rtf(cr[mt][nt][rh * 2 + 1]);
                vi.x = rtf(ci[mt][nt][rh * 2 + 0]);
                vi.y = rtf(ci[mt][nt][rh * 2 + 1]);
                int bb2 = bh >> 3, hh = bh & 7;
                long long o = ((long long)r * 8 + bb2) * 512 + hh * 64 + colL;
                *(float2*)(Cr + o) = vr;
                *(float2*)(Ci + o) = vi;
            }
        }
    }
}

__global__ __launch_bounds__(256)
void round_copy_kernel(const float4* __restrict__ src, float4* __restrict__ dst, int n4)
{
    int i = blockIdx.x * 256 + threadIdx.x;
    if (i < n4) {
        float4 v = src[i];
        uint4 u;
        u.x = f2tf32(v.x); u.y = f2tf32(v.y); u.z = f2tf32(v.z); u.w = f2tf32(v.w);
        *(uint4*)(dst + i) = u;
    }
}

__global__ __launch_bounds__(256)
void reshape_qk_kernel(const float* __restrict__ y, float* __restrict__ q, float* __restrict__ k)
{
    long long idx = (long long)blockIdx.x * 256 + threadIdx.x;   // < 2^24
    int n       = (int)(idx & 1023);
    long long m = (idx >> 10) & 8191;
    int ri      = (int)(idx >> 23);
    float val = rtf(y[(long long)ri * RIY + m * 1536 + n]);
    int t = (int)(m >> 3), b = (int)(m & 7);
    int sec = n >> 9, e = n & 511;
    int h = e >> 6, d = e & 63;
    long long dst = (((long long)ri * 64 + b * 8 + h) * 1024 + t) * 64 + d;
    (sec ? k : q)[dst] = val;
}

__global__ void transpose_v_kernel(const float* __restrict__ y, float* __restrict__ vT)
{
    __shared__ float tile[32][33];
    int zb = blockIdx.z;
    int ri = zb >> 6, bh = zb & 63;
    int b = bh >> 3, h = bh & 7;
    int t0 = blockIdx.x * 32, d0 = blockIdx.y * 32;
    const float* src = y + (long long)ri * RIY + 1024 + (long long)h * 64 + d0;
    #pragma unroll
    for (int r = 0; r < 32; r += 8) {
        int tloc = threadIdx.y + r;
        long long m = (long long)(t0 + tloc) * 8 + b;
        tile[tloc][threadIdx.x] = src[m * 1536 + threadIdx.x];
    }
    __syncthreads();
    float* dst = vT + (((long long)ri * 64 + bh) * 64 + d0) * 1024 + t0;
    #pragma unroll
    for (int r = 0; r < 32; r += 8) {
        int d = threadIdx.y + r;
        dst[(long long)d * 1024 + threadIdx.x] = rtf(tile[threadIdx.x][d]);
    }
}

// Reads raw scores once; writes per-row (max, invZ) and the head-averaged aw.
__global__ __launch_bounds__(128)
void stats_avg_kernel(const float* __restrict__ s, float* __restrict__ avg,
                      float* __restrict__ gm, float* __restrict__ gz)
{
    const int t  = blockIdx.x;
    const int b  = blockIdx.y;
    const int ri = blockIdx.z;
    const int tid = threadIdx.x;
    const int w = tid >> 5;
    __shared__ float redm[4];
    __shared__ float reds[4];

    float4 acc0 = make_float4(0.f, 0.f, 0.f, 0.f);
    float4 acc1 = make_float4(0.f, 0.f, 0.f, 0.f);

    for (int h = 0; h < 8; h++) {
        const float4* p4 = (const float4*)(s + (((long long)ri * 64 + b * 8 + h) * 1024 + t) * 1024);
        float4 v0 = p4[tid];
        float4 v1 = p4[tid + 128];
        float mx = fmaxf(fmaxf(fmaxf(v0.x, v0.y), fmaxf(v0.z, v0.w)),
                         fmaxf(fmaxf(v1.x, v1.y), fmaxf(v1.z, v1.w)));
        #pragma unroll
        for (int o = 16; o > 0; o >>= 1)
            mx = fmaxf(mx, __shfl_xor_sync(0xffffffffu, mx, o));
        if ((tid & 31) == 0) redm[w] = mx;
        __syncthreads();
        mx = fmaxf(fmaxf(redm[0], redm[1]), fmaxf(redm[2], redm[3]));

        float e[8];
        e[0] = __expf(v0.x - mx); e[1] = __expf(v0.y - mx);
        e[2] = __expf(v0.z - mx); e[3] = __expf(v0.w - mx);
        e[4] = __expf(v1.x - mx); e[5] = __expf(v1.y - mx);
        e[6] = __expf(v1.z - mx); e[7] = __expf(v1.w - mx);
        float sum = ((e[0] + e[1]) + (e[2] + e[3])) + ((e[4] + e[5]) + (e[6] + e[7]));
        #pragma unroll
        for (int o = 16; o > 0; o >>= 1)
            sum += __shfl_xor_sync(0xffffffffu, sum, o);
        if ((tid & 31) == 0) reds[w] = sum;
        __syncthreads();
        sum = (reds[0] + reds[1]) + (reds[2] + reds[3]);
        float inv = 1.0f / sum;

        if (tid == 0) {
            int row = ri * 65536 + (b * 8 + h) * 1024 + t;
            gm[row] = mx;
            gz[row] = inv;
        }

        acc0.x += e[0] * inv; acc0.y += e[1] * inv; acc0.z += e[2] * inv; acc0.w += e[3] * inv;
        acc1.x += e[4] * inv; acc1.y += e[5] * inv; acc1.z += e[6] * inv; acc1.w += e[7] * inv;
        __syncthreads();
    }

    float4* o4 = (float4*)(avg + (((long long)ri * 8 + b) * 1024 + t) * 1024);
    acc0.x *= 0.125f; acc0.y *= 0.125f; acc0.z *= 0.125f; acc0.w *= 0.125f;
    acc1.x *= 0.125f; acc1.y *= 0.125f; acc1.z *= 0.125f; acc1.w *= 0.125f;
    o4[tid] = acc0;
    o4[tid + 128] = acc1;
}

extern "C" void kernel_launch(void* const* d_in, const int* in_sizes, int n_in,
                              void* d_out, int out_size)
{
    const float* xr   = (const float*)d_in[0];
    const float* xi   = (const float*)d_in[1];
    const float* Wqr  = (const float*)d_in[2];
    const float* Wqi  = (const float*)d_in[3];
    const float* bqr  = (const float*)d_in[4];
    const float* bqi  = (const float*)d_in[5];
    const float* Wor  = (const float*)d_in[6];
    const float* Woi  = (const float*)d_in[7];
    const float* bor_ = (const float*)d_in[8];
    const float* boi  = (const float*)d_in[9];
    float* out = (float*)d_out;

    float *y, *q, *k, *vT, *s, *att2, *x, *wq, *wo, *sm_, *sz;
    cudaGetSymbolAddress((void**)&y, g_y);
    cudaGetSymbolAddress((void**)&q, g_q);
    cudaGetSymbolAddress((void**)&k, g_k);
    cudaGetSymbolAddress((void**)&vT, g_vT);
    cudaGetSymbolAddress((void**)&s, g_s);
    cudaGetSymbolAddress((void**)&att2, g_att2);
    cudaGetSymbolAddress((void**)&x, g_x);
    cudaGetSymbolAddress((void**)&wq, g_wq);
    cudaGetSymbolAddress((void**)&wo, g_wo);
    cudaGetSymbolAddress((void**)&sm_, g_m);
    cudaGetSymbolAddress((void**)&sz, g_z);

    const int SMEM_PIPE = 3 * 7680 * 4;                 // 92160 B
    const int SMEM_PV   = (2 * 5120 + 3 * 2560) * 4;    // 71680 B

    cudaFuncSetAttribute(gemm_cplx_pipe<-1, 1, true, 0>,
                         cudaFuncAttributeMaxDynamicSharedMemorySize, SMEM_PIPE);
    cudaFuncSetAttribute(gemm_cplx_pipe<1, -1, false, 0>,
                         cudaFuncAttributeMaxDynamicSharedMemorySize, SMEM_PIPE);
    cudaFuncSetAttribute(gemm_pv_soft,
                         cudaFuncAttributeMaxDynamicSharedMemorySize, SMEM_PV);

    // 0) tf32-round inputs and weights into scratch
    round_copy_kernel<<<4096, 256>>>((const float4*)xr, (float4*)x, 1048576);
    round_copy_kernel<<<4096, 256>>>((const float4*)xi, (float4*)(x + RIX), 1048576);
    round_copy_kernel<<<768, 256>>>((const float4*)Wqr, (float4*)wq, 196608);
    round_copy_kernel<<<768, 256>>>((const float4*)Wqi, (float4*)(wq + RIWQ), 196608);
    round_copy_kernel<<<256, 256>>>((const float4*)Wor, (float4*)wo, 65536);
    round_copy_kernel<<<256, 256>>>((const float4*)Woi, (float4*)(wo + RIWO), 65536);

    // 1) QKV complex projection
    gemm_cplx_pipe<-1, 1, true, 0><<<dim3(24, 64, 1), 256, SMEM_PIPE>>>(
        x, x + RIX, wq, wq + RIWQ, bqr, bqi, y, y + RIY,
        1536, 512, 1.0f, 0, 0, 0);

    // 2) head-layout reshapes
    reshape_qk_kernel<<<65536, 256>>>(y, q, k);
    transpose_v_kernel<<<dim3(32, 2, 128), dim3(32, 8)>>>(y, vT);

    // 3) raw scores (batched over 64 heads)
    gemm_cplx_pipe<1, -1, false, 0><<<dim3(16, 8, 64), 256, SMEM_PIPE>>>(
        q, q + RIH, k, k + RIH, nullptr, nullptr, s, s + RIS,
        1024, 64, SCALE_F, 1024LL * 64, 1024LL * 64, 1024LL * 1024);

    // 4) stats (m, invZ) + head-averaged aw into d_out tail; NO writeback
    stats_avg_kernel<<<dim3(1024, 8, 2), 128>>>(s, out + 2 * RIO, sm_, sz);

    // 5) PV: softmax on A-load, cp.async B, epilogue writes [T,B,E] (rounded)
    gemm_pv_soft<<<dim3(1, 8, 64), 256, SMEM_PV>>>(s, vT, sm_, sz, att2, att2 + RIO);

    // 6) output projection into d_out head
    gemm_cplx_pipe<-1, 1, true, 0><<<dim3(8, 64, 1), 256, SMEM_PIPE>>>(
        att2, att2 + RIO, wo, wo + RIWO, bor_, boi, out, out + RIO,
        512, 512, 1.0f, 0, 0, 0);
}